// round 17
// baseline (speedup 1.0000x reference)
#include <cuda_runtime.h>

#define NMAX    160000
#define KCOUT   32
#define KCIN    32
#define KTAPS   27
#define WELEMS  (KTAPS * KCIN * KCOUT)   // 27648
#define DBLOCKS_MAX 625                  // ceil(NMAX/256)
#define EBLOCKS 1184                     // extras: 4 warps/block -> 4736 warps
#define EWARPS  (EBLOCKS * 4)

// ---- device scratch (no allocations allowed) ----
__device__ float g_conv[(size_t)NMAX * KCOUT];   // conv output (dense, then +extras)
__device__ float g_wt[WELEMS];                   // transposed weights [k][c/4][d][c%4] (extras path)
__device__ float g_dsum[DBLOCKS_MAX * KCOUT];    // dense per-block channel sums
__device__ float g_dsq [DBLOCKS_MAX * KCOUT];
__device__ float g_esum[EBLOCKS * KCOUT];        // extras per-block delta sums
__device__ float g_esq [EBLOCKS * KCOUT];
__device__ float g_scale[KCOUT];                 // rstd * gamma
__device__ float g_shift[KCOUT];                 // beta - mean * scale

// packed f32x2 FMA (per-lane IEEE RN, identical numerics to scalar FFMA)
__device__ __forceinline__ unsigned long long ffma2(
    unsigned long long a, unsigned long long b, unsigned long long c) {
    unsigned long long d;
    asm("fma.rn.f32x2 %0, %1, %2, %3;" : "=l"(d) : "l"(a), "l"(b), "l"(c));
    return d;
}
__device__ __forceinline__ unsigned long long pack2(float v) {
    unsigned long long p;
    asm("mov.b64 %0, {%1, %1};" : "=l"(p) : "f"(v));
    return p;
}

// ---------------------------------------------------------------------------
// K0: transpose weight [k][c][d] -> [k][c>>2][d][c&3] for the extras path
//     (lane d loads a float4 covering 4 consecutive c, coalesced).
// ---------------------------------------------------------------------------
__global__ void transpose_w_kernel(const float* __restrict__ w) {
    int i = blockIdx.x * blockDim.x + threadIdx.x;
    if (i < WELEMS) {
        int d = i & 31;
        int c = (i >> 5) & 31;
        int k = i >> 10;
        g_wt[k * 1024 + (c >> 2) * 128 + d * 4 + (c & 3)] = w[i];
    }
}

// ---------------------------------------------------------------------------
// K1a: DENSE pass. Center tap (k=13) == row itself (submanifold identity),
//      so this is a dense [N,32]x[32,32] GEMM: thread-per-row, W13 broadcast
//      from SMEM, 16 packed f32x2 accumulators via fma.rn.f32x2 (halves the
//      FMA issue count). No idx traffic, no divergence. Also accumulates
//      per-block BN partials. Bias omitted (cancels in training-mode BN).
// ---------------------------------------------------------------------------
__global__ __launch_bounds__(256) void dense_kernel(
    const float* __restrict__ feat,   // [N,32]
    const float* __restrict__ w,      // [27,32,32] original layout
    int n)
{
    __shared__ float s_w13[1024];          // W[13][c][d], d contiguous
    __shared__ float s_out[8][32][33];     // [warp][channel][row] (+1 pad)
    __shared__ float s_red[2][8][32];

    const int tid  = threadIdx.x;
    const int lane = tid & 31;
    const int wloc = tid >> 5;

    // cooperative load of center-tap weights (256 x 16B = 4KB exactly)
    ((float4*)s_w13)[tid] = __ldg((const float4*)(w + 13 * 1024) + tid);
    __syncthreads();

    const int row = blockIdx.x * 256 + tid;   // thread owns this row

    unsigned long long acc[16];               // channels {2p, 2p+1} packed
    #pragma unroll
    for (int p = 0; p < 16; ++p) acc[p] = 0ull;

    if (row < n) {
        const float4* fp = (const float4*)(feat + (long)row * 32);
        float4 f[8];
        #pragma unroll
        for (int t = 0; t < 8; ++t) f[t] = __ldg(fp + t);

        #pragma unroll
        for (int c4 = 0; c4 < 8; ++c4) {
            #pragma unroll
            for (int cc = 0; cc < 4; ++cc) {
                const float fc = (cc == 0) ? f[c4].x : (cc == 1) ? f[c4].y
                               : (cc == 2) ? f[c4].z : f[c4].w;
                const unsigned long long fpk = pack2(fc);
                const ulonglong2* wr =
                    (const ulonglong2*)(s_w13 + (c4 * 4 + cc) * 32);
                #pragma unroll
                for (int j = 0; j < 8; ++j) {
                    ulonglong2 wv = wr[j];                 // LDS128 broadcast
                    acc[2*j]   = ffma2(fpk, wv.x, acc[2*j]);
                    acc[2*j+1] = ffma2(fpk, wv.y, acc[2*j+1]);
                }
            }
        }
    }

    // stage: unpack pairs -> s_out[w][channel][row-lane]  (conflict-free)
    #pragma unroll
    for (int p = 0; p < 16; ++p) {
        float lo, hi;
        asm("mov.b64 {%0, %1}, %2;" : "=f"(lo), "=f"(hi) : "l"(acc[p]));
        s_out[wloc][2*p][lane]   = lo;
        s_out[wloc][2*p+1][lane] = hi;
    }
    __syncwarp();

    // per-row finish: lane = channel; coalesced store + BN partials
    const int base = blockIdx.x * 256 + wloc * 32;
    float bsum = 0.f, bsq = 0.f;
    #pragma unroll 4
    for (int r = 0; r < 32; ++r) {
        if (base + r < n) {
            float v = s_out[wloc][lane][r];
            g_conv[(long)(base + r) * KCOUT + lane] = v;
            bsum += v;
            bsq  += v * v;
        }
    }

    s_red[0][wloc][lane] = bsum;
    s_red[1][wloc][lane] = bsq;
    __syncthreads();
    if (tid < 32) {
        float s = 0.f, q = 0.f;
        #pragma unroll
        for (int i = 0; i < 8; ++i) { s += s_red[0][i][tid]; q += s_red[1][i][tid]; }
        g_dsum[blockIdx.x * 32 + tid] = s;
        g_dsq [blockIdx.x * 32 + tid] = q;
    }
}

// ---------------------------------------------------------------------------
// K1b: EXTRAS pass. Warp-per-row; ~61% of rows have zero extra taps and cost
//      only an idx load + ballot (prefetch depth 1). Rows with extras RMW
//      g_conv and accumulate exact delta stats: dsq = d*(2v+d).
// ---------------------------------------------------------------------------
__global__ __launch_bounds__(128, 8) void extras_kernel(
    const float* __restrict__ feat,   // [N,32]
    const int*   __restrict__ nbr,    // [N,27]
    int n)
{
    __shared__ float s_red[2][4][32];

    const int lane = threadIdx.x & 31;
    const int wloc = threadIdx.x >> 5;
    const int warp = blockIdx.x * 4 + wloc;

    const unsigned EXTRA_MASK = ((1u << KTAPS) - 1u) & ~(1u << 13);

    const int per = (n + EWARPS - 1) / EWARPS;
    const int r0  = warp * per;
    const int r1  = (r0 + per < n) ? (r0 + per) : n;

    float bsum = 0.f, bsq = 0.f;

    int idxN = (r0 < r1 && lane < KTAPS) ? __ldg(nbr + (long)r0 * KTAPS + lane) : -1;

    for (int row = r0; row < r1; ++row) {
        const int idx = idxN;
        if (row + 1 < r1) {
            int t = __ldg(nbr + (long)(row + 1) * KTAPS + lane);
            idxN = (lane < KTAPS) ? t : -1;
        }

        unsigned m = __ballot_sync(0xffffffffu, idx >= 0) & EXTRA_MASK;
        if (m) {                                    // warp-uniform branch
            float v = g_conv[(long)row * KCOUT + lane];
            float d = 0.f;
            while (m) {
                int k = __ffs(m) - 1;
                m &= (m - 1);
                int j = __shfl_sync(0xffffffffu, idx, k);

                const float4* fp2 = (const float4*)(feat + (long)j * 32);
                const float4* wp  = (const float4*)(g_wt + k * 1024) + lane;

                float e0 = 0.f, e1 = 0.f;
                #pragma unroll
                for (int h = 0; h < 4; ++h) {
                    float4 fa = __ldg(fp2 + 2*h);
                    float4 fb = __ldg(fp2 + 2*h + 1);
                    float4 wa = __ldg(wp + (2*h) * 32);
                    float4 wb = __ldg(wp + (2*h + 1) * 32);
                    e0 += fa.x*wa.x + fa.y*wa.y + fa.z*wa.z + fa.w*wa.w;
                    e1 += fb.x*wb.x + fb.y*wb.y + fb.z*wb.z + fb.w*wb.w;
                }
                d += e0 + e1;
            }
            g_conv[(long)row * KCOUT + lane] = v + d;
            bsum += d;
            bsq  += d * (2.f * v + d);              // (v+d)^2 - v^2
        }
    }

    s_red[0][wloc][lane] = bsum;
    s_red[1][wloc][lane] = bsq;
    __syncthreads();
    if (threadIdx.x < 32) {
        float s = 0.f, q = 0.f;
        #pragma unroll
        for (int i = 0; i < 4; ++i) { s += s_red[0][i][threadIdx.x]; q += s_red[1][i][threadIdx.x]; }
        g_esum[blockIdx.x * 32 + threadIdx.x] = s;
        g_esq [blockIdx.x * 32 + threadIdx.x] = q;
    }
}

// ---------------------------------------------------------------------------
// K2: reduce both partial sets -> mean/var -> fused scale/shift. One block.
// ---------------------------------------------------------------------------
__global__ void stats_kernel(const float* __restrict__ gamma,
                             const float* __restrict__ beta,
                             int n, int db)
{
    __shared__ float ss[32][32];
    __shared__ float sq[32][32];
    const int ch = threadIdx.x & 31;
    const int sl = threadIdx.x >> 5;   // 1024 threads -> 32 slices

    float s = 0.f, q = 0.f;
    for (int i = sl; i < db; i += 32) {
        s += g_dsum[i * 32 + ch];
        q += g_dsq [i * 32 + ch];
    }
    for (int i = sl; i < EBLOCKS; i += 32) {
        s += g_esum[i * 32 + ch];
        q += g_esq [i * 32 + ch];
    }
    ss[sl][ch] = s;
    sq[sl][ch] = q;
    __syncthreads();

    if (threadIdx.x < 32) {
        float S = 0.f, Q = 0.f;
        #pragma unroll
        for (int i = 0; i < 32; ++i) { S += ss[i][threadIdx.x]; Q += sq[i][threadIdx.x]; }
        float inv_n = 1.f / (float)n;
        float mean  = S * inv_n;
        float var   = Q * inv_n - mean * mean;
        float rstd  = rsqrtf(var + 1e-5f);
        float sc    = rstd * __ldg(gamma + threadIdx.x);
        g_scale[threadIdx.x] = sc;
        g_shift[threadIdx.x] = __ldg(beta + threadIdx.x) - mean * sc;
    }
}

// ---------------------------------------------------------------------------
// K3: elementwise BN-apply + LeakyReLU, float4 vectorized.
// ---------------------------------------------------------------------------
__global__ __launch_bounds__(256) void finalize_kernel(float* __restrict__ out, int n4) {
    int i = blockIdx.x * blockDim.x + threadIdx.x;
    if (i >= n4) return;
    float4 v = ((const float4*)g_conv)[i];
    int cb = (i & 7) * 4;                       // channel base within row
    float4 sc = *(const float4*)(g_scale + cb);
    float4 sh = *(const float4*)(g_shift + cb);
    float4 o;
    o.x = v.x * sc.x + sh.x;
    o.y = v.y * sc.y + sh.y;
    o.z = v.z * sc.z + sh.z;
    o.w = v.w * sc.w + sh.w;
    o.x = (o.x >= 0.f) ? o.x : 0.01f * o.x;
    o.y = (o.y >= 0.f) ? o.y : 0.01f * o.y;
    o.z = (o.z >= 0.f) ? o.z : 0.01f * o.z;
    o.w = (o.w >= 0.f) ? o.w : 0.01f * o.w;
    ((float4*)out)[i] = o;
}

// ---------------------------------------------------------------------------
// kernel_launch — inputs per metadata order:
//   0: features [N,32] f32   1: neighbor_idx [N,27] i32   2: weight [27,32,32] f32
//   3: bias [32] f32 (unused: cancels in training-mode BN)
//   4: gamma [32] f32        5: beta [32] f32
// output: [N,32] f32
// ---------------------------------------------------------------------------
extern "C" void kernel_launch(void* const* d_in, const int* in_sizes, int n_in,
                              void* d_out, int out_size)
{
    const float* feat  = (const float*)d_in[0];
    const int*   nbr   = (const int*)  d_in[1];
    const float* w     = (const float*)d_in[2];
    const float* gamma = (const float*)d_in[4];
    const float* beta  = (const float*)d_in[5];
    float* out = (float*)d_out;

    int n = in_sizes[0] / KCIN;     // number of active voxels
    if (n > NMAX) n = NMAX;
    const int db = (n + 255) / 256;

    transpose_w_kernel<<<(WELEMS + 255) / 256, 256>>>(w);
    dense_kernel<<<db, 256>>>(feat, w, n);
    extras_kernel<<<EBLOCKS, 128>>>(feat, nbr, n);
    stats_kernel<<<1, 1024>>>(gamma, beta, n, db);
    int n4 = n * (KCOUT / 4);
    finalize_kernel<<<(n4 + 255) / 256, 256>>>(out, n4);
}